// round 15
// baseline (speedup 1.0000x reference)
#include <cuda_runtime.h>
#include <cuda_bf16.h>
#include <cuda_fp16.h>
#include <cstdint>

#define NP 100000
#define NA 50000
#define DIM 128
#define EE  500000
#define E2  (2 * EE)

#define NT_P 782            // ceil(NP/128) paper tiles
#define NT_A 391            // ceil(NA/128) author tiles
#define NT   (NT_P + NT_A)
#define NCTA_P 122          // paper CTAs
#define NCTA_A 30           // author CTAs
#define GRID_PERS (NCTA_P + NCTA_A)   // 152 = GB300 SM count

#define NBLK 391            // ceil(NP/256) scan blocks

#if defined(__CUDA_ARCH__) && defined(__CUDA_ARCH_FEAT_SM103_ALL)
#define USE_TC 1
#else
#define USE_TC 0
#endif

// ---------------------------------------------------------------------------
// Scratch (allocation-guard-safe __device__ globals)
__device__ __half g_Hc[(size_t)NP * DIM];         // x_paper  @ W_cites (fp16)
__device__ __half g_Hw[(size_t)NA * DIM];         // x_author @ W_writes (fp16)
__device__ float g_Wf[3][DIM * DIM];              // swizzled f32 W^T images:
                                                  // [0]=cites [1]=writes [2]=self
// CSR-by-dst machinery
__device__ int g_cnt[NP];
__device__ int g_off[NP];
__device__ int g_cur[NP];
__device__ int g_bsum[NBLK + 1];
__device__ int g_boff[NBLK + 1];
__device__ unsigned g_esrc[E2];                   // src | (rel<<31), grouped by dst

// ---------------------------------------------------------------------------
// Swizzled byte offset of f32 element (r,k) in a 128x128 f32 K-major
// blocked-atom tile: atom = 8 rows x 32 f32 (1024B), 16 atom-rows x 4
// atom-cols. SW128 swizzle on top.
__device__ __forceinline__ uint32_t f32_off(int r, int k) {
    uint32_t b = (uint32_t)(((r >> 3) + (k >> 5) * 16) * 1024
                            + (r & 7) * 128 + (k & 31) * 4);
    return b ^ ((b >> 3) & 0x70);
}

#if USE_TC
// ---------------------------------------------------------------------------
// PTX helpers (sm_103a tcgen05, cg1) — only on the 'a' target.
__device__ __forceinline__ uint32_t s2u(const void* p) {
    uint32_t a;
    asm("{ .reg .u64 t; cvta.to.shared.u64 t, %1; cvt.u32.u64 %0, t; }"
        : "=r"(a) : "l"(p));
    return a;
}
__device__ __forceinline__ bool elect1() {
    uint32_t p;
    asm volatile("{ .reg .pred p; elect.sync _|p, 0xFFFFFFFF; selp.b32 %0,1,0,p; }"
                 : "=r"(p));
    return p != 0;
}
// idesc kind::tf32: dtype=F32(1<<4), atype=TF32(2<<7), btype=TF32(2<<10),
// (N/8)<<17, (M/16)<<24  -> M=128, N=128
#define IDESC_TF32_128 0x8200910u

__device__ __forceinline__ void mma_tf32_ss(uint32_t d, uint64_t a, uint64_t b,
                                            uint32_t en) {
    asm volatile(
        "{\n\t.reg .pred p;\n\tsetp.ne.u32 p, %4, 0;\n\t"
        "tcgen05.mma.cta_group::1.kind::tf32 [%0], %1, %2, %3, {%5,%5,%5,%5}, p;\n\t}"
        :: "r"(d), "l"(a), "l"(b), "r"(IDESC_TF32_128), "r"(en), "r"(0u)
        : "memory");
}
#define TC_ALLOC(sa, n)  asm volatile("tcgen05.alloc.cta_group::1.sync.aligned.shared::cta.b32 [%0], %1;" :: "r"(sa), "r"(n) : "memory")
#define TC_DEALLOC(t, n) asm volatile("tcgen05.dealloc.cta_group::1.sync.aligned.b32 %0, %1;" :: "r"(t), "r"(n))
#define TC_RELINQ()      asm volatile("tcgen05.relinquish_alloc_permit.cta_group::1.sync.aligned;")
#define TC_COMMIT(mb)    asm volatile("tcgen05.commit.cta_group::1.mbarrier::arrive::one.shared::cluster.b64 [%0];" :: "r"(mb) : "memory")
#define TC_WAIT_LD()     asm volatile("tcgen05.wait::ld.sync.aligned;" ::: "memory")
#define TC_FENCE_BEFORE() asm volatile("tcgen05.fence::before_thread_sync;" ::: "memory")
#define TC_FENCE_AFTER()  asm volatile("tcgen05.fence::after_thread_sync;" ::: "memory")
#define MBAR_INIT(mb, c) asm volatile("mbarrier.init.shared.b64 [%0], %1;" :: "r"(mb), "r"(c) : "memory")
#define MBAR_INVAL(mb)   asm volatile("mbarrier.inval.shared.b64 [%0];" :: "r"(mb) : "memory")
#define MBAR_WAIT(mb, ph) do {                                                      \
    uint32_t _m = (mb), _p = (ph), _d;                                              \
    asm volatile("{ .reg .pred p; mbarrier.try_wait.parity.acquire.cta.shared::cta.b64 p, [%1], %2; selp.b32 %0,1,0,p; }" \
                 : "=r"(_d) : "r"(_m), "r"(_p) : "memory");                         \
    if (!_d) {                                                                      \
        asm volatile("{ .reg .pred P1; WL_%=: mbarrier.try_wait.parity.acquire.cta.shared::cta.b64 P1, [%0], %1, 0x989680; @P1 bra.uni WD_%=; bra.uni WL_%=; WD_%=: }" \
                     :: "r"(_m), "r"(_p) : "memory");                               \
    }                                                                               \
} while (0)
#define LDTM_X32(r, a)                                                              \
    asm volatile("tcgen05.ld.sync.aligned.32x32b.x32.b32 "                          \
        "{%0,%1,%2,%3,%4,%5,%6,%7,%8,%9,%10,%11,%12,%13,%14,%15,"                   \
        "%16,%17,%18,%19,%20,%21,%22,%23,%24,%25,%26,%27,%28,%29,%30,%31}, [%32];"  \
        : "=r"((r)[0]),"=r"((r)[1]),"=r"((r)[2]),"=r"((r)[3]),                      \
          "=r"((r)[4]),"=r"((r)[5]),"=r"((r)[6]),"=r"((r)[7]),                      \
          "=r"((r)[8]),"=r"((r)[9]),"=r"((r)[10]),"=r"((r)[11]),                    \
          "=r"((r)[12]),"=r"((r)[13]),"=r"((r)[14]),"=r"((r)[15]),                  \
          "=r"((r)[16]),"=r"((r)[17]),"=r"((r)[18]),"=r"((r)[19]),                  \
          "=r"((r)[20]),"=r"((r)[21]),"=r"((r)[22]),"=r"((r)[23]),                  \
          "=r"((r)[24]),"=r"((r)[25]),"=r"((r)[26]),"=r"((r)[27]),                  \
          "=r"((r)[28]),"=r"((r)[29]),"=r"((r)[30]),"=r"((r)[31])                   \
        : "r"(a))

// SMEM descriptor: SW128, version=1(Blackwell), LBO=1, SBO=64 (K-major)
static __device__ __forceinline__ uint64_t smem_desc(uint32_t addr) {
    const uint64_t base = (uint64_t(2) << 61) | (uint64_t(1) << 46)
                        | (uint64_t(64) << 32) | (uint64_t(1) << 16);
    return base | ((uint64_t)(addr >> 4) & 0x3FFF);
}

// Full 128x128 K=128 tf32 gemm into D: 16 K-steps of K=8.
__device__ __forceinline__ void issue_tf32(uint32_t d, uint64_t da, uint64_t db) {
    uint32_t en = 0;
    #pragma unroll
    for (int g = 0; g < 4; g++)
        #pragma unroll
        for (int s = 0; s < 4; s++) {
            uint64_t off = (uint64_t)(g * 1024 + s * 2);
            mma_tf32_ss(d, da + off, db + off, en);
            en = 1;
        }
}

// Non-blocking cp.async of one 128x128 f32 X tile into swizzled SMEM A.
__device__ __forceinline__ void copy_a_async(
    const float* __restrict__ X, int row0, int n_rows, uint32_t sA_u, int tid)
{
    #pragma unroll
    for (int kk = 0; kk < 16; kk++) {
        int i = tid + kk * 256;              // 0..4095 float4
        int r = i >> 5, j = i & 31;
        int gr = row0 + r;
        uint32_t dst = sA_u + f32_off(r, j * 4);
        const float* src = X + (size_t)gr * DIM + j * 4;
        int sz = (gr < n_rows) ? 16 : 0;
        asm volatile("cp.async.cg.shared.global [%0], [%1], 16, %2;"
                     :: "r"(dst), "l"(src), "r"(sz) : "memory");
    }
    asm volatile("cp.async.commit_group;" ::: "memory");
}
#define CP_WAIT_ALL() asm volatile("cp.async.wait_group 0;" ::: "memory")

// Shared staging step: LDTM D -> swizzled f32 STS into sbuf (one 64-row chunk).
__device__ __forceinline__ void stage_chunk(
    uint32_t dtm, int c, char* sbuf, int w, int lane)
{
    int sub = w & 3;
    if ((sub >> 1) == c) {
        uint32_t c0 = (uint32_t)(w >> 2) * 64;
        uint32_t d[64];
        LDTM_X32(d, dtm + c0);
        LDTM_X32(d + 32, dtm + c0 + 32);
        TC_WAIT_LD();
        int lrow = (sub & 1) * 32 + lane;
        #pragma unroll
        for (int j = 0; j < 16; j++) {
            int col4 = (int)(c0 >> 2) + j;
            int g = col4 ^ (lrow & 31);
            *(float4*)(sbuf + lrow * 512 + g * 16) =
                make_float4(__uint_as_float(d[4 * j + 0]),
                            __uint_as_float(d[4 * j + 1]),
                            __uint_as_float(d[4 * j + 2]),
                            __uint_as_float(d[4 * j + 3]));
        }
    }
    __syncthreads();
}

// Staged D store, f32 output (for d_out).
__device__ __forceinline__ void store_d_f32(
    float* __restrict__ Y, int row0, int n_rows, uint32_t dtm,
    char* sbuf, int tid, int w, int lane)
{
    #pragma unroll
    for (int c = 0; c < 2; c++) {
        stage_chunk(dtm, c, sbuf, w, lane);
        #pragma unroll
        for (int k = 0; k < 8; k++) {
            int i = tid + k * 256;
            int r = i >> 5, j = i & 31;
            int gr = row0 + c * 64 + r;
            if (gr < n_rows) {
                int g = j ^ (r & 31);
                float4 v = *(const float4*)(sbuf + r * 512 + g * 16);
                ((float4*)(Y + (size_t)gr * DIM))[j] = v;
            }
        }
        __syncthreads();
    }
}

// Staged D store, fp16 output (for g_Hc / g_Hw). Coalesced 8B stores.
__device__ __forceinline__ void store_d_f16(
    __half* __restrict__ Y, int row0, int n_rows, uint32_t dtm,
    char* sbuf, int tid, int w, int lane)
{
    #pragma unroll
    for (int c = 0; c < 2; c++) {
        stage_chunk(dtm, c, sbuf, w, lane);
        #pragma unroll
        for (int k = 0; k < 8; k++) {
            int i = tid + k * 256;
            int r = i >> 5, j = i & 31;
            int gr = row0 + c * 64 + r;
            if (gr < n_rows) {
                int g = j ^ (r & 31);
                float4 v = *(const float4*)(sbuf + r * 512 + g * 16);
                __half2 h01 = __floats2half2_rn(v.x, v.y);
                __half2 h23 = __floats2half2_rn(v.z, v.w);
                ((uint2*)(Y + (size_t)gr * DIM))[j] =
                    make_uint2(*(uint32_t*)&h01, *(uint32_t*)&h23);
            }
        }
        __syncthreads();
    }
}
#endif // USE_TC

// ---------------------------------------------------------------------------
// All three W matrices -> swizzled f32 W^T images, pre-rounded to tf32 (rna).
__global__ void __launch_bounds__(256) wconv_kernel(
    const float* __restrict__ W0, const float* __restrict__ W1,
    const float* __restrict__ W2)
{
    int i = blockIdx.x * 256 + threadIdx.x;
    if (i >= 3 * DIM * DIM) return;
    int m = i >> 14, e = i & (DIM * DIM - 1);
    const float* W = (m == 0) ? W0 : (m == 1) ? W1 : W2;
    int k = e >> 7, n = e & 127;
    float x = W[e];                                     // W[k][n]
    uint32_t xb;
#if USE_TC
    asm("cvt.rna.tf32.f32 %0, %1;" : "=r"(xb) : "f"(x));
#else
    xb = __float_as_uint(x);
#endif
    g_Wf[m][f32_off(n, k) >> 2] = __uint_as_float(xb);
}

// ---------------------------------------------------------------------------
// CSR build: histogram, 3-step scan, fill.
__global__ void __launch_bounds__(256) hist_kernel(
    const int* __restrict__ c_dst, const int* __restrict__ w_dst)
{
    int e = blockIdx.x * 256 + threadIdx.x;
    if (e >= E2) return;
    int d = (e < EE) ? __ldg(c_dst + e) : __ldg(w_dst + e - EE);
    atomicAdd(&g_cnt[d], 1);
}

__global__ void __launch_bounds__(256) scan_a_kernel() {
    __shared__ int sm[256];
    int b = blockIdx.x, t = threadIdx.x;
    int i = b * 256 + t;
    int v = (i < NP) ? g_cnt[i] : 0;
    sm[t] = v;
    __syncthreads();
    int acc = v;
    #pragma unroll
    for (int s = 1; s < 256; s <<= 1) {
        int add = (t >= s) ? sm[t - s] : 0;
        __syncthreads();
        acc += add;
        sm[t] = acc;
        __syncthreads();
    }
    if (i < NP) g_off[i] = acc - v;
    if (t == 255) g_bsum[b] = acc;
}

__global__ void __launch_bounds__(512) scan_b_kernel() {
    __shared__ int sm[512];
    int t = threadIdx.x;
    int v = (t < NBLK) ? g_bsum[t] : 0;
    sm[t] = v;
    __syncthreads();
    int acc = v;
    #pragma unroll
    for (int s = 1; s < 512; s <<= 1) {
        int add = (t >= s) ? sm[t - s] : 0;
        __syncthreads();
        acc += add;
        sm[t] = acc;
        __syncthreads();
    }
    if (t < NBLK) g_boff[t] = acc - v;
}

__global__ void __launch_bounds__(256) scan_c_kernel() {
    int b = blockIdx.x, t = threadIdx.x;
    int i = b * 256 + t;
    if (i < NP) {
        int o = g_off[i] + g_boff[b];
        g_off[i] = o;
        g_cur[i] = o;
    }
}

__global__ void __launch_bounds__(256) fill_kernel(
    const int* __restrict__ c_src, const int* __restrict__ c_dst,
    const int* __restrict__ w_src, const int* __restrict__ w_dst)
{
    int e = blockIdx.x * 256 + threadIdx.x;
    if (e >= E2) return;
    int d;
    unsigned sv;
    if (e < EE) {
        d = __ldg(c_dst + e);
        sv = (unsigned)__ldg(c_src + e);
    } else {
        d = __ldg(w_dst + e - EE);
        sv = (unsigned)__ldg(w_src + e - EE) | 0x80000000u;
    }
    int pos = atomicAdd(&g_cur[d], 1);
    g_esrc[pos] = sv;
}

// ---------------------------------------------------------------------------
// Pull aggregation + fused finalize. One warp per paper node. fp16 messages.
__global__ void __launch_bounds__(256) aggregate_kernel(
    float* __restrict__ out, const float* __restrict__ bias)
{
    int d    = (blockIdx.x * 256 + threadIdx.x) >> 5;
    int lane = threadIdx.x & 31;
    if (d >= NP) return;

    const int n    = g_cnt[d];
    const int base = g_off[d];

    float4 acc = make_float4(0.f, 0.f, 0.f, 0.f);
    int j = 0;
    for (; j + 4 <= n; j += 4) {
        uint2 u[4];
        #pragma unroll
        for (int q = 0; q < 4; q++) {
            unsigned s = __ldg(&g_esrc[base + j + q]);
            const __half* H = (s & 0x80000000u) ? g_Hw : g_Hc;
            u[q] = __ldg((const uint2*)(H + (size_t)(s & 0x7FFFFFFFu) * DIM)
                         + lane);
        }
        #pragma unroll
        for (int q = 0; q < 4; q++) {
            float2 f01 = __half22float2(*(__half2*)&u[q].x);
            float2 f23 = __half22float2(*(__half2*)&u[q].y);
            acc.x += f01.x; acc.y += f01.y;
            acc.z += f23.x; acc.w += f23.y;
        }
    }
    for (; j < n; j++) {
        unsigned s = __ldg(&g_esrc[base + j]);
        const __half* H = (s & 0x80000000u) ? g_Hw : g_Hc;
        uint2 u = __ldg((const uint2*)(H + (size_t)(s & 0x7FFFFFFFu) * DIM)
                        + lane);
        float2 f01 = __half22float2(*(__half2*)&u.x);
        float2 f23 = __half22float2(*(__half2*)&u.y);
        acc.x += f01.x; acc.y += f01.y;
        acc.z += f23.x; acc.w += f23.y;
    }

    const float inv = 1.0f / (float)(n + 1);
    float4* op = (float4*)(out + (size_t)d * DIM) + lane;
    float4 self = *op;
    float4 b = ((const float4*)bias)[lane];
    float4 r;
    r.x = fmaxf(fmaf((self.x + acc.x), inv, b.x), 0.f);
    r.y = fmaxf(fmaf((self.y + acc.y), inv, b.y), 0.f);
    r.z = fmaxf(fmaf((self.z + acc.z), inv, b.z), 0.f);
    r.w = fmaxf(fmaf((self.w + acc.w), inv, b.w), 0.f);
    *op = r;
}

// ---------------------------------------------------------------------------
// ===== Persistent CTA-specialized tf32 GEMM, D double-buffered, async A =====
// MMA(t+1) issued BEFORE epilogue(t): its execution hides under the epilogue.
// SMEM: hdr 1KB | B0 64KB | B1 64KB | A 64KB | sbuf 32KB = 230400.
#define G_MB0  8
#define G_MB1  16
#define G_B0   1024
#define G_B1   (G_B0 + 65536)
#define G_A    (G_B1 + 65536)
#define G_SB   (G_A + 65536)
#define G_TOTAL (G_SB + 32768)      // 230400 <= 232448

__global__ void __launch_bounds__(256, 1) gemm_mega_kernel(
    const float* __restrict__ xp, const float* __restrict__ xa,
    const float* __restrict__ Wc_f, const float* __restrict__ Ww_f,
    const float* __restrict__ Ws_f,
    float* __restrict__ out, __half* __restrict__ Hc, __half* __restrict__ Hw)
{
    extern __shared__ char smem[];
    const int tid = threadIdx.x, w = tid >> 5, lane = tid & 31;

#if USE_TC
    uint32_t sb = s2u(smem);
    char* sbuf = smem + G_SB;
    const uint32_t sA_u = sb + G_A;

    if (w == 0) {
        TC_ALLOC(sb, 512);
        TC_RELINQ();
    }
    if (tid == 0) {
        MBAR_INIT(sb + G_MB0, 1);
        MBAR_INIT(sb + G_MB1, 1);
    }

    // CTA role
    const int paper = (blockIdx.x < NCTA_P);
    const float* X;
    int t0, stride, tend, nr;
    if (paper) {
        X = xp; t0 = blockIdx.x;          stride = NCTA_P; tend = NT_P; nr = NP;
    } else {
        X = xa; t0 = blockIdx.x - NCTA_P; stride = NCTA_A; tend = NT_A; nr = NA;
    }

    // Stage B images from pre-built g_Wf (straight float4 copies)
    {
        const float* B0s = paper ? g_Wf[2] : g_Wf[1];
        for (int i = tid; i < 4096; i += 256)
            ((float4*)(smem + G_B0))[i] = ((const float4*)B0s)[i];
        if (paper)
            for (int i = tid; i < 4096; i += 256)
                ((float4*)(smem + G_B1))[i] = ((const float4*)g_Wf[0])[i];
    }
    asm volatile("fence.proxy.async.shared::cta;" ::: "memory");
    __syncthreads();

    uint32_t tmem;
    asm volatile("ld.shared.b32 %0, [%1];" : "=r"(tmem) : "r"(sb));

    const uint64_t dB0 = smem_desc(sb + G_B0);
    const uint64_t dB1 = smem_desc(sb + G_B1);
    const uint64_t dA  = smem_desc(sA_u);

    // Prologue: A(t0) + MMA into slot 0
    int t = t0;
    copy_a_async(X, t * 128, nr, sA_u, tid);
    CP_WAIT_ALL();
    asm volatile("fence.proxy.async.shared::cta;" ::: "memory");
    __syncthreads();
    if (w == 0 && elect1()) {
        issue_tf32(tmem + 0, dA, dB0);
        if (paper) issue_tf32(tmem + 128, dA, dB1);
        TC_COMMIT(sb + G_MB0);
    }

    int i = 0;
    for (; t < tend; t += stride, i++) {
        const int s  = i & 1;
        const int ph = (i >> 1) & 1;
        const int row0 = t * 128;

        MBAR_WAIT(sb + (s ? G_MB1 : G_MB0), ph);   // MMA(t) done: A free, D[s] full
        TC_FENCE_AFTER();

        // A(t+1): async copy, short exposed wait, then issue MMA(t+1) into the
        // OTHER D slot BEFORE the epilogue -> MMA executes under the epilogue.
        int tn = t + stride;
        if (tn < tend) {
            copy_a_async(X, tn * 128, nr, sA_u, tid);
            CP_WAIT_ALL();
            asm volatile("fence.proxy.async.shared::cta;" ::: "memory");
            __syncthreads();
            if (w == 0 && elect1()) {
                uint32_t ds = (uint32_t)(s ^ 1) * 256;
                issue_tf32(tmem + ds, dA, dB0);
                if (paper) issue_tf32(tmem + ds + 128, dA, dB1);
                TC_COMMIT(sb + ((s ^ 1) ? G_MB1 : G_MB0));
            }
        }

        // Epilogue slot s (overlaps MMA(t+1) execution)
        if (paper) {
            store_d_f32(out, row0, nr, tmem + (uint32_t)s * 256,
                        sbuf, tid, w, lane);
            store_d_f16(Hc, row0, nr, tmem + (uint32_t)s * 256 + 128,
                        sbuf, tid, w, lane);
        } else {
            store_d_f16(Hw, row0, nr, tmem + (uint32_t)s * 256,
                        sbuf, tid, w, lane);
        }
        TC_FENCE_BEFORE();
    }

    __syncthreads();
    if (tid == 0) {
        MBAR_INVAL(sb + G_MB0);
        MBAR_INVAL(sb + G_MB1);
    }
    __syncthreads();
    if (w == 0) TC_DEALLOC(tmem, 512);
#else
    // -------- SIMT fallback (non-'a' PTX target only; never runs on GB300) --
    (void)smem;
    for (int t = blockIdx.x; t < NT; t += GRID_PERS) {
        const int paper = (t < NT_P);
        const int row0  = (paper ? t : t - NT_P) * 128;
        const int nr    = paper ? NP : NA;
        const float* X  = paper ? xp : xa;
        const int nw    = paper ? 2 : 1;
        for (int m = 0; m < nw; m++) {
            const float* Wf = paper ? (m ? Wc_f : Ws_f) : Ww_f;
            float acc[16][4];
            #pragma unroll
            for (int r = 0; r < 16; r++)
                acc[r][0] = acc[r][1] = acc[r][2] = acc[r][3] = 0.f;
            for (int k4 = 0; k4 < 32; k4++) {
                float4 w0 = __ldg((const float4*)(Wf + (k4 * 4 + 0) * DIM) + lane);
                float4 w1 = __ldg((const float4*)(Wf + (k4 * 4 + 1) * DIM) + lane);
                float4 w2 = __ldg((const float4*)(Wf + (k4 * 4 + 2) * DIM) + lane);
                float4 w3 = __ldg((const float4*)(Wf + (k4 * 4 + 3) * DIM) + lane);
                for (int r = 0; r < 16; r++) {
                    int gr = row0 + w + 8 * r;
                    float4 xv = (gr < nr)
                        ? __ldg((const float4*)(X + (size_t)gr * DIM) + k4)
                        : make_float4(0.f, 0.f, 0.f, 0.f);
                    acc[r][0] += xv.x * w0.x + xv.y * w1.x + xv.z * w2.x + xv.w * w3.x;
                    acc[r][1] += xv.x * w0.y + xv.y * w1.y + xv.z * w2.y + xv.w * w3.y;
                    acc[r][2] += xv.x * w0.z + xv.y * w1.z + xv.z * w2.z + xv.w * w3.z;
                    acc[r][3] += xv.x * w0.w + xv.y * w1.w + xv.z * w2.w + xv.w * w3.w;
                }
            }
            #pragma unroll
            for (int r = 0; r < 16; r++) {
                int gr = row0 + w + 8 * r;
                if (gr >= nr) continue;
                if (paper && m == 0) {
                    ((float4*)(out + (size_t)gr * DIM))[lane] =
                        make_float4(acc[r][0], acc[r][1], acc[r][2], acc[r][3]);
                } else {
                    __half* Y = paper ? Hc : Hw;
                    __half2 h01 = __floats2half2_rn(acc[r][0], acc[r][1]);
                    __half2 h23 = __floats2half2_rn(acc[r][2], acc[r][3]);
                    ((uint2*)(Y + (size_t)gr * DIM))[lane] =
                        make_uint2(*(uint32_t*)&h01, *(uint32_t*)&h23);
                }
            }
        }
    }
#endif
}

// ---------------------------------------------------------------------------
extern "C" void kernel_launch(void* const* d_in, const int* in_sizes, int n_in,
                              void* d_out, int out_size)
{
    const float* x_paper    = (const float*)d_in[0];
    const float* x_author   = (const float*)d_in[1];
    const float* W_cites    = (const float*)d_in[2];
    const float* W_writes   = (const float*)d_in[3];
    const float* W_self     = (const float*)d_in[4];
    const float* bias       = (const float*)d_in[5];
    const int*   cites_src  = (const int*)d_in[6];
    const int*   cites_dst  = (const int*)d_in[7];
    const int*   writes_src = (const int*)d_in[8];
    const int*   writes_dst = (const int*)d_in[9];
    float*       out        = (float*)d_out;

    cudaFuncSetAttribute(gemm_mega_kernel,
                         cudaFuncAttributeMaxDynamicSharedMemorySize, G_TOTAL);

    void *pHc = nullptr, *pHw = nullptr, *pCnt = nullptr;
    cudaGetSymbolAddress(&pHc, g_Hc);
    cudaGetSymbolAddress(&pHw, g_Hw);
    cudaGetSymbolAddress(&pCnt, g_cnt);

    // Fork a side stream for the CSR chain (graph-capture-legal fork/join).
    cudaStream_t s2;
    cudaStreamCreateWithFlags(&s2, cudaStreamNonBlocking);
    cudaEvent_t ev_fork, ev_join;
    cudaEventCreateWithFlags(&ev_fork, cudaEventDisableTiming);
    cudaEventCreateWithFlags(&ev_join, cudaEventDisableTiming);

    cudaEventRecord(ev_fork, 0);
    cudaStreamWaitEvent(s2, ev_fork, 0);

    // --- side stream: CSR build ---
    cudaMemsetAsync(pCnt, 0, NP * sizeof(int), s2);
    hist_kernel<<<(E2 + 255) / 256, 256, 0, s2>>>(cites_dst, writes_dst);
    scan_a_kernel<<<NBLK, 256, 0, s2>>>();
    scan_b_kernel<<<1, 512, 0, s2>>>();
    scan_c_kernel<<<NBLK, 256, 0, s2>>>();
    fill_kernel<<<(E2 + 255) / 256, 256, 0, s2>>>(cites_src, cites_dst,
                                                  writes_src, writes_dst);
    cudaEventRecord(ev_join, s2);

    // --- main stream: W images + persistent pipelined GEMM ---
    wconv_kernel<<<(3 * DIM * DIM + 255) / 256, 256>>>(W_cites, W_writes, W_self);
    gemm_mega_kernel<<<GRID_PERS, 256, G_TOTAL>>>(
        x_paper, x_author, W_cites, W_writes, W_self,
        out, (__half*)pHc, (__half*)pHw);

    // join: aggregate needs both chains
    cudaStreamWaitEvent(0, ev_join, 0);
    aggregate_kernel<<<(NP * 32 + 255) / 256, 256>>>(out, bias);

    cudaEventDestroy(ev_fork);
    cudaEventDestroy(ev_join);
    cudaStreamDestroy(s2);
}

// round 16
// speedup vs baseline: 1.3656x; 1.3656x over previous
#include <cuda_runtime.h>
#include <cuda_bf16.h>
#include <cuda_fp16.h>
#include <cstdint>

#define NP 100000
#define NA 50000
#define DIM 128
#define EE  500000
#define E2  (2 * EE)

#define NT_P 782            // ceil(NP/128) paper tiles
#define NT_A 391            // ceil(NA/128) author tiles
#define NT   (NT_P + NT_A)
#define NCTA_P 122          // paper CTAs
#define NCTA_A 30           // author CTAs
#define GRID_PERS (NCTA_P + NCTA_A)   // 152 = GB300 SM count

#define NBLK 391            // ceil(NP/256) scan blocks

#if defined(__CUDA_ARCH__) && defined(__CUDA_ARCH_FEAT_SM103_ALL)
#define USE_TC 1
#else
#define USE_TC 0
#endif

// ---------------------------------------------------------------------------
// Scratch (allocation-guard-safe __device__ globals)
__device__ __half g_Hc[(size_t)NP * DIM];         // x_paper  @ W_cites (fp16)
__device__ __half g_Hw[(size_t)NA * DIM];         // x_author @ W_writes (fp16)
__device__ float g_Wf[3][DIM * DIM];              // swizzled f32 W^T images:
                                                  // [0]=cites [1]=writes [2]=self
// CSR-by-dst machinery
__device__ int g_cnt[NP];
__device__ int g_off[NP];
__device__ int g_cur[NP];
__device__ int g_bsum[NBLK + 1];
__device__ int g_boff[NBLK + 1];
__device__ unsigned g_esrc[E2];                   // src | (rel<<31), grouped by dst

// ---------------------------------------------------------------------------
// Swizzled byte offset of f32 element (r,k) in a 128x128 f32 K-major
// blocked-atom tile: atom = 8 rows x 32 f32 (1024B), 16 atom-rows x 4
// atom-cols. SW128 swizzle on top.
__device__ __forceinline__ uint32_t f32_off(int r, int k) {
    uint32_t b = (uint32_t)(((r >> 3) + (k >> 5) * 16) * 1024
                            + (r & 7) * 128 + (k & 31) * 4);
    return b ^ ((b >> 3) & 0x70);
}

#if USE_TC
// ---------------------------------------------------------------------------
// PTX helpers (sm_103a tcgen05, cg1) — only on the 'a' target.
__device__ __forceinline__ uint32_t s2u(const void* p) {
    uint32_t a;
    asm("{ .reg .u64 t; cvta.to.shared.u64 t, %1; cvt.u32.u64 %0, t; }"
        : "=r"(a) : "l"(p));
    return a;
}
__device__ __forceinline__ bool elect1() {
    uint32_t p;
    asm volatile("{ .reg .pred p; elect.sync _|p, 0xFFFFFFFF; selp.b32 %0,1,0,p; }"
                 : "=r"(p));
    return p != 0;
}
// idesc kind::tf32: dtype=F32(1<<4), atype=TF32(2<<7), btype=TF32(2<<10),
// (N/8)<<17, (M/16)<<24  -> M=128, N=128
#define IDESC_TF32_128 0x8200910u

__device__ __forceinline__ void mma_tf32_ss(uint32_t d, uint64_t a, uint64_t b,
                                            uint32_t en) {
    asm volatile(
        "{\n\t.reg .pred p;\n\tsetp.ne.u32 p, %4, 0;\n\t"
        "tcgen05.mma.cta_group::1.kind::tf32 [%0], %1, %2, %3, {%5,%5,%5,%5}, p;\n\t}"
        :: "r"(d), "l"(a), "l"(b), "r"(IDESC_TF32_128), "r"(en), "r"(0u)
        : "memory");
}
#define TC_ALLOC(sa, n)  asm volatile("tcgen05.alloc.cta_group::1.sync.aligned.shared::cta.b32 [%0], %1;" :: "r"(sa), "r"(n) : "memory")
#define TC_DEALLOC(t, n) asm volatile("tcgen05.dealloc.cta_group::1.sync.aligned.b32 %0, %1;" :: "r"(t), "r"(n))
#define TC_RELINQ()      asm volatile("tcgen05.relinquish_alloc_permit.cta_group::1.sync.aligned;")
#define TC_COMMIT(mb)    asm volatile("tcgen05.commit.cta_group::1.mbarrier::arrive::one.shared::cluster.b64 [%0];" :: "r"(mb) : "memory")
#define TC_WAIT_LD()     asm volatile("tcgen05.wait::ld.sync.aligned;" ::: "memory")
#define TC_FENCE_BEFORE() asm volatile("tcgen05.fence::before_thread_sync;" ::: "memory")
#define TC_FENCE_AFTER()  asm volatile("tcgen05.fence::after_thread_sync;" ::: "memory")
#define MBAR_INIT(mb, c) asm volatile("mbarrier.init.shared.b64 [%0], %1;" :: "r"(mb), "r"(c) : "memory")
#define MBAR_INVAL(mb)   asm volatile("mbarrier.inval.shared.b64 [%0];" :: "r"(mb) : "memory")
#define MBAR_WAIT(mb, ph) do {                                                      \
    uint32_t _m = (mb), _p = (ph), _d;                                              \
    asm volatile("{ .reg .pred p; mbarrier.try_wait.parity.acquire.cta.shared::cta.b64 p, [%1], %2; selp.b32 %0,1,0,p; }" \
                 : "=r"(_d) : "r"(_m), "r"(_p) : "memory");                         \
    if (!_d) {                                                                      \
        asm volatile("{ .reg .pred P1; WL_%=: mbarrier.try_wait.parity.acquire.cta.shared::cta.b64 P1, [%0], %1, 0x989680; @P1 bra.uni WD_%=; bra.uni WL_%=; WD_%=: }" \
                     :: "r"(_m), "r"(_p) : "memory");                               \
    }                                                                               \
} while (0)
#define LDTM_X32(r, a)                                                              \
    asm volatile("tcgen05.ld.sync.aligned.32x32b.x32.b32 "                          \
        "{%0,%1,%2,%3,%4,%5,%6,%7,%8,%9,%10,%11,%12,%13,%14,%15,"                   \
        "%16,%17,%18,%19,%20,%21,%22,%23,%24,%25,%26,%27,%28,%29,%30,%31}, [%32];"  \
        : "=r"((r)[0]),"=r"((r)[1]),"=r"((r)[2]),"=r"((r)[3]),                      \
          "=r"((r)[4]),"=r"((r)[5]),"=r"((r)[6]),"=r"((r)[7]),                      \
          "=r"((r)[8]),"=r"((r)[9]),"=r"((r)[10]),"=r"((r)[11]),                    \
          "=r"((r)[12]),"=r"((r)[13]),"=r"((r)[14]),"=r"((r)[15]),                  \
          "=r"((r)[16]),"=r"((r)[17]),"=r"((r)[18]),"=r"((r)[19]),                  \
          "=r"((r)[20]),"=r"((r)[21]),"=r"((r)[22]),"=r"((r)[23]),                  \
          "=r"((r)[24]),"=r"((r)[25]),"=r"((r)[26]),"=r"((r)[27]),                  \
          "=r"((r)[28]),"=r"((r)[29]),"=r"((r)[30]),"=r"((r)[31])                   \
        : "r"(a))

// SMEM descriptor: SW128, version=1(Blackwell), LBO=1, SBO=64 (K-major)
static __device__ __forceinline__ uint64_t smem_desc(uint32_t addr) {
    const uint64_t base = (uint64_t(2) << 61) | (uint64_t(1) << 46)
                        | (uint64_t(64) << 32) | (uint64_t(1) << 16);
    return base | ((uint64_t)(addr >> 4) & 0x3FFF);
}

// Full 128x128 K=128 tf32 gemm into D: 16 K-steps of K=8.
__device__ __forceinline__ void issue_tf32(uint32_t d, uint64_t da, uint64_t db) {
    uint32_t en = 0;
    #pragma unroll
    for (int g = 0; g < 4; g++)
        #pragma unroll
        for (int s = 0; s < 4; s++) {
            uint64_t off = (uint64_t)(g * 1024 + s * 2);
            mma_tf32_ss(d, da + off, db + off, en);
            en = 1;
        }
}

// Non-blocking cp.async of one 128x128 f32 X tile into swizzled SMEM A.
__device__ __forceinline__ void copy_a_async(
    const float* __restrict__ X, int row0, int n_rows, uint32_t sA_u, int tid)
{
    #pragma unroll
    for (int kk = 0; kk < 16; kk++) {
        int i = tid + kk * 256;              // 0..4095 float4
        int r = i >> 5, j = i & 31;
        int gr = row0 + r;
        uint32_t dst = sA_u + f32_off(r, j * 4);
        const float* src = X + (size_t)gr * DIM + j * 4;
        int sz = (gr < n_rows) ? 16 : 0;
        asm volatile("cp.async.cg.shared.global [%0], [%1], 16, %2;"
                     :: "r"(dst), "l"(src), "r"(sz) : "memory");
    }
    asm volatile("cp.async.commit_group;" ::: "memory");
}
#define CP_WAIT_ALL() asm volatile("cp.async.wait_group 0;" ::: "memory")

// Shared staging step: LDTM D -> swizzled f32 STS into sbuf (one 64-row chunk).
__device__ __forceinline__ void stage_chunk(
    uint32_t dtm, int c, char* sbuf, int w, int lane)
{
    int sub = w & 3;
    if ((sub >> 1) == c) {
        uint32_t c0 = (uint32_t)(w >> 2) * 64;
        uint32_t d[64];
        LDTM_X32(d, dtm + c0);
        LDTM_X32(d + 32, dtm + c0 + 32);
        TC_WAIT_LD();
        int lrow = (sub & 1) * 32 + lane;
        #pragma unroll
        for (int j = 0; j < 16; j++) {
            int col4 = (int)(c0 >> 2) + j;
            int g = col4 ^ (lrow & 31);
            *(float4*)(sbuf + lrow * 512 + g * 16) =
                make_float4(__uint_as_float(d[4 * j + 0]),
                            __uint_as_float(d[4 * j + 1]),
                            __uint_as_float(d[4 * j + 2]),
                            __uint_as_float(d[4 * j + 3]));
        }
    }
    __syncthreads();
}

// Staged D store, f32 output (for d_out).
__device__ __forceinline__ void store_d_f32(
    float* __restrict__ Y, int row0, int n_rows, uint32_t dtm,
    char* sbuf, int tid, int w, int lane)
{
    #pragma unroll
    for (int c = 0; c < 2; c++) {
        stage_chunk(dtm, c, sbuf, w, lane);
        #pragma unroll
        for (int k = 0; k < 8; k++) {
            int i = tid + k * 256;
            int r = i >> 5, j = i & 31;
            int gr = row0 + c * 64 + r;
            if (gr < n_rows) {
                int g = j ^ (r & 31);
                float4 v = *(const float4*)(sbuf + r * 512 + g * 16);
                ((float4*)(Y + (size_t)gr * DIM))[j] = v;
            }
        }
        __syncthreads();
    }
}

// Staged D store, fp16 output (for g_Hc / g_Hw). Coalesced 8B stores.
__device__ __forceinline__ void store_d_f16(
    __half* __restrict__ Y, int row0, int n_rows, uint32_t dtm,
    char* sbuf, int tid, int w, int lane)
{
    #pragma unroll
    for (int c = 0; c < 2; c++) {
        stage_chunk(dtm, c, sbuf, w, lane);
        #pragma unroll
        for (int k = 0; k < 8; k++) {
            int i = tid + k * 256;
            int r = i >> 5, j = i & 31;
            int gr = row0 + c * 64 + r;
            if (gr < n_rows) {
                int g = j ^ (r & 31);
                float4 v = *(const float4*)(sbuf + r * 512 + g * 16);
                __half2 h01 = __floats2half2_rn(v.x, v.y);
                __half2 h23 = __floats2half2_rn(v.z, v.w);
                ((uint2*)(Y + (size_t)gr * DIM))[j] =
                    make_uint2(*(uint32_t*)&h01, *(uint32_t*)&h23);
            }
        }
        __syncthreads();
    }
}
#endif // USE_TC

// ---------------------------------------------------------------------------
// All three W matrices -> swizzled f32 W^T images, pre-rounded to tf32 (rna).
__global__ void __launch_bounds__(256) wconv_kernel(
    const float* __restrict__ W0, const float* __restrict__ W1,
    const float* __restrict__ W2)
{
    int i = blockIdx.x * 256 + threadIdx.x;
    if (i >= 3 * DIM * DIM) return;
    int m = i >> 14, e = i & (DIM * DIM - 1);
    const float* W = (m == 0) ? W0 : (m == 1) ? W1 : W2;
    int k = e >> 7, n = e & 127;
    float x = W[e];                                     // W[k][n]
    uint32_t xb;
#if USE_TC
    asm("cvt.rna.tf32.f32 %0, %1;" : "=r"(xb) : "f"(x));
#else
    xb = __float_as_uint(x);
#endif
    g_Wf[m][f32_off(n, k) >> 2] = __uint_as_float(xb);
}

// ---------------------------------------------------------------------------
// CSR build: histogram, 3-step scan, fill.
__global__ void __launch_bounds__(256) hist_kernel(
    const int* __restrict__ c_dst, const int* __restrict__ w_dst)
{
    int e = blockIdx.x * 256 + threadIdx.x;
    if (e >= E2) return;
    int d = (e < EE) ? __ldg(c_dst + e) : __ldg(w_dst + e - EE);
    atomicAdd(&g_cnt[d], 1);
}

__global__ void __launch_bounds__(256) scan_a_kernel() {
    __shared__ int sm[256];
    int b = blockIdx.x, t = threadIdx.x;
    int i = b * 256 + t;
    int v = (i < NP) ? g_cnt[i] : 0;
    sm[t] = v;
    __syncthreads();
    int acc = v;
    #pragma unroll
    for (int s = 1; s < 256; s <<= 1) {
        int add = (t >= s) ? sm[t - s] : 0;
        __syncthreads();
        acc += add;
        sm[t] = acc;
        __syncthreads();
    }
    if (i < NP) g_off[i] = acc - v;
    if (t == 255) g_bsum[b] = acc;
}

__global__ void __launch_bounds__(512) scan_b_kernel() {
    __shared__ int sm[512];
    int t = threadIdx.x;
    int v = (t < NBLK) ? g_bsum[t] : 0;
    sm[t] = v;
    __syncthreads();
    int acc = v;
    #pragma unroll
    for (int s = 1; s < 512; s <<= 1) {
        int add = (t >= s) ? sm[t - s] : 0;
        __syncthreads();
        acc += add;
        sm[t] = acc;
        __syncthreads();
    }
    if (t < NBLK) g_boff[t] = acc - v;
}

__global__ void __launch_bounds__(256) scan_c_kernel() {
    int b = blockIdx.x, t = threadIdx.x;
    int i = b * 256 + t;
    if (i < NP) {
        int o = g_off[i] + g_boff[b];
        g_off[i] = o;
        g_cur[i] = o;
    }
}

__global__ void __launch_bounds__(256) fill_kernel(
    const int* __restrict__ c_src, const int* __restrict__ c_dst,
    const int* __restrict__ w_src, const int* __restrict__ w_dst)
{
    int e = blockIdx.x * 256 + threadIdx.x;
    if (e >= E2) return;
    int d;
    unsigned sv;
    if (e < EE) {
        d = __ldg(c_dst + e);
        sv = (unsigned)__ldg(c_src + e);
    } else {
        d = __ldg(w_dst + e - EE);
        sv = (unsigned)__ldg(w_src + e - EE) | 0x80000000u;
    }
    int pos = atomicAdd(&g_cur[d], 1);
    g_esrc[pos] = sv;
}

// ---------------------------------------------------------------------------
// Pull aggregation + fused finalize. One warp per paper node. fp16 messages.
__global__ void __launch_bounds__(256) aggregate_kernel(
    float* __restrict__ out, const float* __restrict__ bias)
{
    int d    = (blockIdx.x * 256 + threadIdx.x) >> 5;
    int lane = threadIdx.x & 31;
    if (d >= NP) return;

    const int n    = g_cnt[d];
    const int base = g_off[d];

    float4 acc = make_float4(0.f, 0.f, 0.f, 0.f);
    int j = 0;
    for (; j + 4 <= n; j += 4) {
        uint2 u[4];
        #pragma unroll
        for (int q = 0; q < 4; q++) {
            unsigned s = __ldg(&g_esrc[base + j + q]);
            const __half* H = (s & 0x80000000u) ? g_Hw : g_Hc;
            u[q] = __ldg((const uint2*)(H + (size_t)(s & 0x7FFFFFFFu) * DIM)
                         + lane);
        }
        #pragma unroll
        for (int q = 0; q < 4; q++) {
            float2 f01 = __half22float2(*(__half2*)&u[q].x);
            float2 f23 = __half22float2(*(__half2*)&u[q].y);
            acc.x += f01.x; acc.y += f01.y;
            acc.z += f23.x; acc.w += f23.y;
        }
    }
    for (; j < n; j++) {
        unsigned s = __ldg(&g_esrc[base + j]);
        const __half* H = (s & 0x80000000u) ? g_Hw : g_Hc;
        uint2 u = __ldg((const uint2*)(H + (size_t)(s & 0x7FFFFFFFu) * DIM)
                        + lane);
        float2 f01 = __half22float2(*(__half2*)&u.x);
        float2 f23 = __half22float2(*(__half2*)&u.y);
        acc.x += f01.x; acc.y += f01.y;
        acc.z += f23.x; acc.w += f23.y;
    }

    const float inv = 1.0f / (float)(n + 1);
    float4* op = (float4*)(out + (size_t)d * DIM) + lane;
    float4 self = *op;
    float4 b = ((const float4*)bias)[lane];
    float4 r;
    r.x = fmaxf(fmaf((self.x + acc.x), inv, b.x), 0.f);
    r.y = fmaxf(fmaf((self.y + acc.y), inv, b.y), 0.f);
    r.z = fmaxf(fmaf((self.z + acc.z), inv, b.z), 0.f);
    r.w = fmaxf(fmaf((self.w + acc.w), inv, b.w), 0.f);
    *op = r;
}

// ---------------------------------------------------------------------------
// ===== Persistent CTA-specialized tf32 GEMM, D double-buffered, async A =====
// R13 ordering (measured best): wait MMA(t) -> launch cp.async A(t+1) ->
// epilogue(t) [A copy flies under it] -> cp.wait -> commit MMA(t+1).
// (MMA execution cannot overlap LDTM epilogues: TMEM port contention.)
// SMEM: hdr 1KB | B0 64KB | B1 64KB | A 64KB | sbuf 32KB = 230400.
#define G_MB0  8
#define G_MB1  16
#define G_B0   1024
#define G_B1   (G_B0 + 65536)
#define G_A    (G_B1 + 65536)
#define G_SB   (G_A + 65536)
#define G_TOTAL (G_SB + 32768)      // 230400 <= 232448

__global__ void __launch_bounds__(256, 1) gemm_mega_kernel(
    const float* __restrict__ xp, const float* __restrict__ xa,
    const float* __restrict__ Wc_f, const float* __restrict__ Ww_f,
    const float* __restrict__ Ws_f,
    float* __restrict__ out, __half* __restrict__ Hc, __half* __restrict__ Hw)
{
    extern __shared__ char smem[];
    const int tid = threadIdx.x, w = tid >> 5, lane = tid & 31;

#if USE_TC
    uint32_t sb = s2u(smem);
    char* sbuf = smem + G_SB;
    const uint32_t sA_u = sb + G_A;

    if (w == 0) {
        TC_ALLOC(sb, 512);
        TC_RELINQ();
    }
    if (tid == 0) {
        MBAR_INIT(sb + G_MB0, 1);
        MBAR_INIT(sb + G_MB1, 1);
    }

    // CTA role
    const int paper = (blockIdx.x < NCTA_P);
    const float* X;
    int t0, stride, tend, nr;
    if (paper) {
        X = xp; t0 = blockIdx.x;          stride = NCTA_P; tend = NT_P; nr = NP;
    } else {
        X = xa; t0 = blockIdx.x - NCTA_P; stride = NCTA_A; tend = NT_A; nr = NA;
    }

    // Stage B images from pre-built g_Wf (straight float4 copies)
    {
        const float* B0s = paper ? g_Wf[2] : g_Wf[1];
        for (int i = tid; i < 4096; i += 256)
            ((float4*)(smem + G_B0))[i] = ((const float4*)B0s)[i];
        if (paper)
            for (int i = tid; i < 4096; i += 256)
                ((float4*)(smem + G_B1))[i] = ((const float4*)g_Wf[0])[i];
    }
    asm volatile("fence.proxy.async.shared::cta;" ::: "memory");
    __syncthreads();

    uint32_t tmem;
    asm volatile("ld.shared.b32 %0, [%1];" : "=r"(tmem) : "r"(sb));

    const uint64_t dB0 = smem_desc(sb + G_B0);
    const uint64_t dB1 = smem_desc(sb + G_B1);
    const uint64_t dA  = smem_desc(sA_u);

    // Prologue: A(t0) + MMA into slot 0
    int t = t0;
    copy_a_async(X, t * 128, nr, sA_u, tid);
    CP_WAIT_ALL();
    asm volatile("fence.proxy.async.shared::cta;" ::: "memory");
    __syncthreads();
    if (w == 0 && elect1()) {
        issue_tf32(tmem + 0, dA, dB0);
        if (paper) issue_tf32(tmem + 128, dA, dB1);
        TC_COMMIT(sb + G_MB0);
    }

    int i = 0;
    for (; t < tend; t += stride, i++) {
        const int s  = i & 1;
        const int ph = (i >> 1) & 1;
        const int row0 = t * 128;

        MBAR_WAIT(sb + (s ? G_MB1 : G_MB0), ph);   // MMA(t) done: A free, D[s] full
        TC_FENCE_AFTER();

        // Launch async copy of A(t+1); it flies under the epilogue below.
        int tn = t + stride;
        if (tn < tend)
            copy_a_async(X, tn * 128, nr, sA_u, tid);

        // Epilogue slot s (overlaps the async A copy)
        if (paper) {
            store_d_f32(out, row0, nr, tmem + (uint32_t)s * 256,
                        sbuf, tid, w, lane);
            store_d_f16(Hc, row0, nr, tmem + (uint32_t)s * 256 + 128,
                        sbuf, tid, w, lane);
        } else {
            store_d_f16(Hw, row0, nr, tmem + (uint32_t)s * 256,
                        sbuf, tid, w, lane);
        }
        TC_FENCE_BEFORE();

        // A(t+1) landed -> issue MMA(t+1) into the other slot
        if (tn < tend) {
            CP_WAIT_ALL();
            asm volatile("fence.proxy.async.shared::cta;" ::: "memory");
            __syncthreads();
            if (w == 0 && elect1()) {
                uint32_t ds = (uint32_t)(s ^ 1) * 256;
                issue_tf32(tmem + ds, dA, dB0);
                if (paper) issue_tf32(tmem + ds + 128, dA, dB1);
                TC_COMMIT(sb + ((s ^ 1) ? G_MB1 : G_MB0));
            }
        }
    }

    __syncthreads();
    if (tid == 0) {
        MBAR_INVAL(sb + G_MB0);
        MBAR_INVAL(sb + G_MB1);
    }
    __syncthreads();
    if (w == 0) TC_DEALLOC(tmem, 512);
#else
    // -------- SIMT fallback (non-'a' PTX target only; never runs on GB300) --
    (void)smem;
    for (int t = blockIdx.x; t < NT; t += GRID_PERS) {
        const int paper = (t < NT_P);
        const int row0  = (paper ? t : t - NT_P) * 128;
        const int nr    = paper ? NP : NA;
        const float* X  = paper ? xp : xa;
        const int nw    = paper ? 2 : 1;
        for (int m = 0; m < nw; m++) {
            const float* Wf = paper ? (m ? Wc_f : Ws_f) : Ww_f;
            float acc[16][4];
            #pragma unroll
            for (int r = 0; r < 16; r++)
                acc[r][0] = acc[r][1] = acc[r][2] = acc[r][3] = 0.f;
            for (int k4 = 0; k4 < 32; k4++) {
                float4 w0 = __ldg((const float4*)(Wf + (k4 * 4 + 0) * DIM) + lane);
                float4 w1 = __ldg((const float4*)(Wf + (k4 * 4 + 1) * DIM) + lane);
                float4 w2 = __ldg((const float4*)(Wf + (k4 * 4 + 2) * DIM) + lane);
                float4 w3 = __ldg((const float4*)(Wf + (k4 * 4 + 3) * DIM) + lane);
                for (int r = 0; r < 16; r++) {
                    int gr = row0 + w + 8 * r;
                    float4 xv = (gr < nr)
                        ? __ldg((const float4*)(X + (size_t)gr * DIM) + k4)
                        : make_float4(0.f, 0.f, 0.f, 0.f);
                    acc[r][0] += xv.x * w0.x + xv.y * w1.x + xv.z * w2.x + xv.w * w3.x;
                    acc[r][1] += xv.x * w0.y + xv.y * w1.y + xv.z * w2.y + xv.w * w3.y;
                    acc[r][2] += xv.x * w0.z + xv.y * w1.z + xv.z * w2.z + xv.w * w3.z;
                    acc[r][3] += xv.x * w0.w + xv.y * w1.w + xv.z * w2.w + xv.w * w3.w;
                }
            }
            #pragma unroll
            for (int r = 0; r < 16; r++) {
                int gr = row0 + w + 8 * r;
                if (gr >= nr) continue;
                if (paper && m == 0) {
                    ((float4*)(out + (size_t)gr * DIM))[lane] =
                        make_float4(acc[r][0], acc[r][1], acc[r][2], acc[r][3]);
                } else {
                    __half* Y = paper ? Hc : Hw;
                    __half2 h01 = __floats2half2_rn(acc[r][0], acc[r][1]);
                    __half2 h23 = __floats2half2_rn(acc[r][2], acc[r][3]);
                    ((uint2*)(Y + (size_t)gr * DIM))[lane] =
                        make_uint2(*(uint32_t*)&h01, *(uint32_t*)&h23);
                }
            }
        }
    }
#endif
}

// ---------------------------------------------------------------------------
extern "C" void kernel_launch(void* const* d_in, const int* in_sizes, int n_in,
                              void* d_out, int out_size)
{
    const float* x_paper    = (const float*)d_in[0];
    const float* x_author   = (const float*)d_in[1];
    const float* W_cites    = (const float*)d_in[2];
    const float* W_writes   = (const float*)d_in[3];
    const float* W_self     = (const float*)d_in[4];
    const float* bias       = (const float*)d_in[5];
    const int*   cites_src  = (const int*)d_in[6];
    const int*   cites_dst  = (const int*)d_in[7];
    const int*   writes_src = (const int*)d_in[8];
    const int*   writes_dst = (const int*)d_in[9];
    float*       out        = (float*)d_out;

    cudaFuncSetAttribute(gemm_mega_kernel,
                         cudaFuncAttributeMaxDynamicSharedMemorySize, G_TOTAL);

    void *pHc = nullptr, *pHw = nullptr, *pCnt = nullptr;
    cudaGetSymbolAddress(&pHc, g_Hc);
    cudaGetSymbolAddress(&pHw, g_Hw);
    cudaGetSymbolAddress(&pCnt, g_cnt);

    // Fork a side stream for the CSR chain (graph-capture-legal fork/join).
    cudaStream_t s2;
    cudaStreamCreateWithFlags(&s2, cudaStreamNonBlocking);
    cudaEvent_t ev_fork, ev_join;
    cudaEventCreateWithFlags(&ev_fork, cudaEventDisableTiming);
    cudaEventCreateWithFlags(&ev_join, cudaEventDisableTiming);

    cudaEventRecord(ev_fork, 0);
    cudaStreamWaitEvent(s2, ev_fork, 0);

    // --- side stream: CSR build ---
    cudaMemsetAsync(pCnt, 0, NP * sizeof(int), s2);
    hist_kernel<<<(E2 + 255) / 256, 256, 0, s2>>>(cites_dst, writes_dst);
    scan_a_kernel<<<NBLK, 256, 0, s2>>>();
    scan_b_kernel<<<1, 512, 0, s2>>>();
    scan_c_kernel<<<NBLK, 256, 0, s2>>>();
    fill_kernel<<<(E2 + 255) / 256, 256, 0, s2>>>(cites_src, cites_dst,
                                                  writes_src, writes_dst);
    cudaEventRecord(ev_join, s2);

    // --- main stream: W images + persistent pipelined GEMM ---
    wconv_kernel<<<(3 * DIM * DIM + 255) / 256, 256>>>(W_cites, W_writes, W_self);
    gemm_mega_kernel<<<GRID_PERS, 256, G_TOTAL>>>(
        x_paper, x_author, W_cites, W_writes, W_self,
        out, (__half*)pHc, (__half*)pHw);

    // join: aggregate needs both chains
    cudaStreamWaitEvent(0, ev_join, 0);
    aggregate_kernel<<<(NP * 32 + 255) / 256, 256>>>(out, bias);

    cudaEventDestroy(ev_fork);
    cudaEventDestroy(ev_join);
    cudaStreamDestroy(s2);
}

// round 17
// speedup vs baseline: 1.3705x; 1.0036x over previous
#include <cuda_runtime.h>
#include <cuda_bf16.h>
#include <cuda_fp16.h>
#include <cstdint>

#define NP 100000
#define NA 50000
#define DIM 128
#define EE  500000
#define E2  (2 * EE)

#define NT_P 782            // ceil(NP/128) paper tiles
#define NT_A 391            // ceil(NA/128) author tiles
#define NT   (NT_P + NT_A)
#define NCTA_P 116          // paper CTAs  (max 7 tiles -> ~63k cyc)
#define NCTA_A 36           // author CTAs (max 11 tiles -> ~60k cyc)
#define GRID_PERS (NCTA_P + NCTA_A)   // 152 = GB300 SM count

#define NBLK 391            // ceil(NP/256) scan blocks

#if defined(__CUDA_ARCH__) && defined(__CUDA_ARCH_FEAT_SM103_ALL)
#define USE_TC 1
#else
#define USE_TC 0
#endif

// ---------------------------------------------------------------------------
// Scratch (allocation-guard-safe __device__ globals)
__device__ __half g_Hc[(size_t)NP * DIM];         // x_paper  @ W_cites (fp16)
__device__ __half g_Hw[(size_t)NA * DIM];         // x_author @ W_writes (fp16)
__device__ float g_Wf[3][DIM * DIM];              // swizzled f32 W^T images:
                                                  // [0]=cites [1]=writes [2]=self
// CSR-by-dst machinery
__device__ int g_cnt[NP];
__device__ int g_off[NP];
__device__ int g_cur[NP];
__device__ int g_bsum[NBLK + 1];
__device__ int g_boff[NBLK + 1];
__device__ unsigned g_esrc[E2];                   // src | (rel<<31), grouped by dst

// ---------------------------------------------------------------------------
// Swizzled byte offset of f32 element (r,k) in a 128x128 f32 K-major
// blocked-atom tile: atom = 8 rows x 32 f32 (1024B), 16 atom-rows x 4
// atom-cols. SW128 swizzle on top.
__device__ __forceinline__ uint32_t f32_off(int r, int k) {
    uint32_t b = (uint32_t)(((r >> 3) + (k >> 5) * 16) * 1024
                            + (r & 7) * 128 + (k & 31) * 4);
    return b ^ ((b >> 3) & 0x70);
}

#if USE_TC
// ---------------------------------------------------------------------------
// PTX helpers (sm_103a tcgen05, cg1) — only on the 'a' target.
__device__ __forceinline__ uint32_t s2u(const void* p) {
    uint32_t a;
    asm("{ .reg .u64 t; cvta.to.shared.u64 t, %1; cvt.u32.u64 %0, t; }"
        : "=r"(a) : "l"(p));
    return a;
}
__device__ __forceinline__ bool elect1() {
    uint32_t p;
    asm volatile("{ .reg .pred p; elect.sync _|p, 0xFFFFFFFF; selp.b32 %0,1,0,p; }"
                 : "=r"(p));
    return p != 0;
}
// idesc kind::tf32: dtype=F32(1<<4), atype=TF32(2<<7), btype=TF32(2<<10),
// (N/8)<<17, (M/16)<<24  -> M=128, N=128
#define IDESC_TF32_128 0x8200910u

__device__ __forceinline__ void mma_tf32_ss(uint32_t d, uint64_t a, uint64_t b,
                                            uint32_t en) {
    asm volatile(
        "{\n\t.reg .pred p;\n\tsetp.ne.u32 p, %4, 0;\n\t"
        "tcgen05.mma.cta_group::1.kind::tf32 [%0], %1, %2, %3, {%5,%5,%5,%5}, p;\n\t}"
        :: "r"(d), "l"(a), "l"(b), "r"(IDESC_TF32_128), "r"(en), "r"(0u)
        : "memory");
}
#define TC_ALLOC(sa, n)  asm volatile("tcgen05.alloc.cta_group::1.sync.aligned.shared::cta.b32 [%0], %1;" :: "r"(sa), "r"(n) : "memory")
#define TC_DEALLOC(t, n) asm volatile("tcgen05.dealloc.cta_group::1.sync.aligned.b32 %0, %1;" :: "r"(t), "r"(n))
#define TC_RELINQ()      asm volatile("tcgen05.relinquish_alloc_permit.cta_group::1.sync.aligned;")
#define TC_COMMIT(mb)    asm volatile("tcgen05.commit.cta_group::1.mbarrier::arrive::one.shared::cluster.b64 [%0];" :: "r"(mb) : "memory")
#define TC_WAIT_LD()     asm volatile("tcgen05.wait::ld.sync.aligned;" ::: "memory")
#define TC_FENCE_BEFORE() asm volatile("tcgen05.fence::before_thread_sync;" ::: "memory")
#define TC_FENCE_AFTER()  asm volatile("tcgen05.fence::after_thread_sync;" ::: "memory")
#define MBAR_INIT(mb, c) asm volatile("mbarrier.init.shared.b64 [%0], %1;" :: "r"(mb), "r"(c) : "memory")
#define MBAR_INVAL(mb)   asm volatile("mbarrier.inval.shared.b64 [%0];" :: "r"(mb) : "memory")
#define MBAR_WAIT(mb, ph) do {                                                      \
    uint32_t _m = (mb), _p = (ph), _d;                                              \
    asm volatile("{ .reg .pred p; mbarrier.try_wait.parity.acquire.cta.shared::cta.b64 p, [%1], %2; selp.b32 %0,1,0,p; }" \
                 : "=r"(_d) : "r"(_m), "r"(_p) : "memory");                         \
    if (!_d) {                                                                      \
        asm volatile("{ .reg .pred P1; WL_%=: mbarrier.try_wait.parity.acquire.cta.shared::cta.b64 P1, [%0], %1, 0x989680; @P1 bra.uni WD_%=; bra.uni WL_%=; WD_%=: }" \
                     :: "r"(_m), "r"(_p) : "memory");                               \
    }                                                                               \
} while (0)
#define LDTM_X32(r, a)                                                              \
    asm volatile("tcgen05.ld.sync.aligned.32x32b.x32.b32 "                          \
        "{%0,%1,%2,%3,%4,%5,%6,%7,%8,%9,%10,%11,%12,%13,%14,%15,"                   \
        "%16,%17,%18,%19,%20,%21,%22,%23,%24,%25,%26,%27,%28,%29,%30,%31}, [%32];"  \
        : "=r"((r)[0]),"=r"((r)[1]),"=r"((r)[2]),"=r"((r)[3]),                      \
          "=r"((r)[4]),"=r"((r)[5]),"=r"((r)[6]),"=r"((r)[7]),                      \
          "=r"((r)[8]),"=r"((r)[9]),"=r"((r)[10]),"=r"((r)[11]),                    \
          "=r"((r)[12]),"=r"((r)[13]),"=r"((r)[14]),"=r"((r)[15]),                  \
          "=r"((r)[16]),"=r"((r)[17]),"=r"((r)[18]),"=r"((r)[19]),                  \
          "=r"((r)[20]),"=r"((r)[21]),"=r"((r)[22]),"=r"((r)[23]),                  \
          "=r"((r)[24]),"=r"((r)[25]),"=r"((r)[26]),"=r"((r)[27]),                  \
          "=r"((r)[28]),"=r"((r)[29]),"=r"((r)[30]),"=r"((r)[31])                   \
        : "r"(a))

// SMEM descriptor: SW128, version=1(Blackwell), LBO=1, SBO=64 (K-major)
static __device__ __forceinline__ uint64_t smem_desc(uint32_t addr) {
    const uint64_t base = (uint64_t(2) << 61) | (uint64_t(1) << 46)
                        | (uint64_t(64) << 32) | (uint64_t(1) << 16);
    return base | ((uint64_t)(addr >> 4) & 0x3FFF);
}

// Full 128x128 K=128 tf32 gemm into D: 16 K-steps of K=8.
__device__ __forceinline__ void issue_tf32(uint32_t d, uint64_t da, uint64_t db) {
    uint32_t en = 0;
    #pragma unroll
    for (int g = 0; g < 4; g++)
        #pragma unroll
        for (int s = 0; s < 4; s++) {
            uint64_t off = (uint64_t)(g * 1024 + s * 2);
            mma_tf32_ss(d, da + off, db + off, en);
            en = 1;
        }
}

// Non-blocking cp.async of one 128x128 f32 X tile into swizzled SMEM A.
__device__ __forceinline__ void copy_a_async(
    const float* __restrict__ X, int row0, int n_rows, uint32_t sA_u, int tid)
{
    #pragma unroll
    for (int kk = 0; kk < 16; kk++) {
        int i = tid + kk * 256;              // 0..4095 float4
        int r = i >> 5, j = i & 31;
        int gr = row0 + r;
        uint32_t dst = sA_u + f32_off(r, j * 4);
        const float* src = X + (size_t)gr * DIM + j * 4;
        int sz = (gr < n_rows) ? 16 : 0;
        asm volatile("cp.async.cg.shared.global [%0], [%1], 16, %2;"
                     :: "r"(dst), "l"(src), "r"(sz) : "memory");
    }
    asm volatile("cp.async.commit_group;" ::: "memory");
}
#define CP_WAIT_ALL() asm volatile("cp.async.wait_group 0;" ::: "memory")

// Shared staging step: LDTM D -> swizzled f32 STS into sbuf (one 64-row chunk).
__device__ __forceinline__ void stage_chunk(
    uint32_t dtm, int c, char* sbuf, int w, int lane)
{
    int sub = w & 3;
    if ((sub >> 1) == c) {
        uint32_t c0 = (uint32_t)(w >> 2) * 64;
        uint32_t d[64];
        LDTM_X32(d, dtm + c0);
        LDTM_X32(d + 32, dtm + c0 + 32);
        TC_WAIT_LD();
        int lrow = (sub & 1) * 32 + lane;
        #pragma unroll
        for (int j = 0; j < 16; j++) {
            int col4 = (int)(c0 >> 2) + j;
            int g = col4 ^ (lrow & 31);
            *(float4*)(sbuf + lrow * 512 + g * 16) =
                make_float4(__uint_as_float(d[4 * j + 0]),
                            __uint_as_float(d[4 * j + 1]),
                            __uint_as_float(d[4 * j + 2]),
                            __uint_as_float(d[4 * j + 3]));
        }
    }
    __syncthreads();
}

// Staged D store, f32 output (for d_out).
__device__ __forceinline__ void store_d_f32(
    float* __restrict__ Y, int row0, int n_rows, uint32_t dtm,
    char* sbuf, int tid, int w, int lane)
{
    #pragma unroll
    for (int c = 0; c < 2; c++) {
        stage_chunk(dtm, c, sbuf, w, lane);
        #pragma unroll
        for (int k = 0; k < 8; k++) {
            int i = tid + k * 256;
            int r = i >> 5, j = i & 31;
            int gr = row0 + c * 64 + r;
            if (gr < n_rows) {
                int g = j ^ (r & 31);
                float4 v = *(const float4*)(sbuf + r * 512 + g * 16);
                ((float4*)(Y + (size_t)gr * DIM))[j] = v;
            }
        }
        __syncthreads();
    }
}

// Staged D store, fp16 output (for g_Hc / g_Hw). Coalesced 8B stores.
__device__ __forceinline__ void store_d_f16(
    __half* __restrict__ Y, int row0, int n_rows, uint32_t dtm,
    char* sbuf, int tid, int w, int lane)
{
    #pragma unroll
    for (int c = 0; c < 2; c++) {
        stage_chunk(dtm, c, sbuf, w, lane);
        #pragma unroll
        for (int k = 0; k < 8; k++) {
            int i = tid + k * 256;
            int r = i >> 5, j = i & 31;
            int gr = row0 + c * 64 + r;
            if (gr < n_rows) {
                int g = j ^ (r & 31);
                float4 v = *(const float4*)(sbuf + r * 512 + g * 16);
                __half2 h01 = __floats2half2_rn(v.x, v.y);
                __half2 h23 = __floats2half2_rn(v.z, v.w);
                ((uint2*)(Y + (size_t)gr * DIM))[j] =
                    make_uint2(*(uint32_t*)&h01, *(uint32_t*)&h23);
            }
        }
        __syncthreads();
    }
}
#endif // USE_TC

// ---------------------------------------------------------------------------
// All three W matrices -> swizzled f32 W^T images, pre-rounded to tf32 (rna).
__global__ void __launch_bounds__(256) wconv_kernel(
    const float* __restrict__ W0, const float* __restrict__ W1,
    const float* __restrict__ W2)
{
    int i = blockIdx.x * 256 + threadIdx.x;
    if (i >= 3 * DIM * DIM) return;
    int m = i >> 14, e = i & (DIM * DIM - 1);
    const float* W = (m == 0) ? W0 : (m == 1) ? W1 : W2;
    int k = e >> 7, n = e & 127;
    float x = W[e];                                     // W[k][n]
    uint32_t xb;
#if USE_TC
    asm("cvt.rna.tf32.f32 %0, %1;" : "=r"(xb) : "f"(x));
#else
    xb = __float_as_uint(x);
#endif
    g_Wf[m][f32_off(n, k) >> 2] = __uint_as_float(xb);
}

// ---------------------------------------------------------------------------
// CSR build: histogram, 3-step scan, fill.
__global__ void __launch_bounds__(256) hist_kernel(
    const int* __restrict__ c_dst, const int* __restrict__ w_dst)
{
    int e = blockIdx.x * 256 + threadIdx.x;
    if (e >= E2) return;
    int d = (e < EE) ? __ldg(c_dst + e) : __ldg(w_dst + e - EE);
    atomicAdd(&g_cnt[d], 1);
}

__global__ void __launch_bounds__(256) scan_a_kernel() {
    __shared__ int sm[256];
    int b = blockIdx.x, t = threadIdx.x;
    int i = b * 256 + t;
    int v = (i < NP) ? g_cnt[i] : 0;
    sm[t] = v;
    __syncthreads();
    int acc = v;
    #pragma unroll
    for (int s = 1; s < 256; s <<= 1) {
        int add = (t >= s) ? sm[t - s] : 0;
        __syncthreads();
        acc += add;
        sm[t] = acc;
        __syncthreads();
    }
    if (i < NP) g_off[i] = acc - v;
    if (t == 255) g_bsum[b] = acc;
}

__global__ void __launch_bounds__(512) scan_b_kernel() {
    __shared__ int sm[512];
    int t = threadIdx.x;
    int v = (t < NBLK) ? g_bsum[t] : 0;
    sm[t] = v;
    __syncthreads();
    int acc = v;
    #pragma unroll
    for (int s = 1; s < 512; s <<= 1) {
        int add = (t >= s) ? sm[t - s] : 0;
        __syncthreads();
        acc += add;
        sm[t] = acc;
        __syncthreads();
    }
    if (t < NBLK) g_boff[t] = acc - v;
}

__global__ void __launch_bounds__(256) scan_c_kernel() {
    int b = blockIdx.x, t = threadIdx.x;
    int i = b * 256 + t;
    if (i < NP) {
        int o = g_off[i] + g_boff[b];
        g_off[i] = o;
        g_cur[i] = o;
    }
}

__global__ void __launch_bounds__(256) fill_kernel(
    const int* __restrict__ c_src, const int* __restrict__ c_dst,
    const int* __restrict__ w_src, const int* __restrict__ w_dst)
{
    int e = blockIdx.x * 256 + threadIdx.x;
    if (e >= E2) return;
    int d;
    unsigned sv;
    if (e < EE) {
        d = __ldg(c_dst + e);
        sv = (unsigned)__ldg(c_src + e);
    } else {
        d = __ldg(w_dst + e - EE);
        sv = (unsigned)__ldg(w_src + e - EE) | 0x80000000u;
    }
    int pos = atomicAdd(&g_cur[d], 1);
    g_esrc[pos] = sv;
}

// ---------------------------------------------------------------------------
// Pull aggregation + fused finalize. One warp per paper node. fp16 messages.
__global__ void __launch_bounds__(256) aggregate_kernel(
    float* __restrict__ out, const float* __restrict__ bias)
{
    int d    = (blockIdx.x * 256 + threadIdx.x) >> 5;
    int lane = threadIdx.x & 31;
    if (d >= NP) return;

    const int n    = g_cnt[d];
    const int base = g_off[d];

    float4 acc = make_float4(0.f, 0.f, 0.f, 0.f);
    int j = 0;
    for (; j + 4 <= n; j += 4) {
        uint2 u[4];
        #pragma unroll
        for (int q = 0; q < 4; q++) {
            unsigned s = __ldg(&g_esrc[base + j + q]);
            const __half* H = (s & 0x80000000u) ? g_Hw : g_Hc;
            u[q] = __ldg((const uint2*)(H + (size_t)(s & 0x7FFFFFFFu) * DIM)
                         + lane);
        }
        #pragma unroll
        for (int q = 0; q < 4; q++) {
            float2 f01 = __half22float2(*(__half2*)&u[q].x);
            float2 f23 = __half22float2(*(__half2*)&u[q].y);
            acc.x += f01.x; acc.y += f01.y;
            acc.z += f23.x; acc.w += f23.y;
        }
    }
    for (; j < n; j++) {
        unsigned s = __ldg(&g_esrc[base + j]);
        const __half* H = (s & 0x80000000u) ? g_Hw : g_Hc;
        uint2 u = __ldg((const uint2*)(H + (size_t)(s & 0x7FFFFFFFu) * DIM)
                        + lane);
        float2 f01 = __half22float2(*(__half2*)&u.x);
        float2 f23 = __half22float2(*(__half2*)&u.y);
        acc.x += f01.x; acc.y += f01.y;
        acc.z += f23.x; acc.w += f23.y;
    }

    const float inv = 1.0f / (float)(n + 1);
    float4* op = (float4*)(out + (size_t)d * DIM) + lane;
    float4 self = *op;
    float4 b = ((const float4*)bias)[lane];
    float4 r;
    r.x = fmaxf(fmaf((self.x + acc.x), inv, b.x), 0.f);
    r.y = fmaxf(fmaf((self.y + acc.y), inv, b.y), 0.f);
    r.z = fmaxf(fmaf((self.z + acc.z), inv, b.z), 0.f);
    r.w = fmaxf(fmaf((self.w + acc.w), inv, b.w), 0.f);
    *op = r;
}

// ---------------------------------------------------------------------------
// ===== Persistent CTA-specialized tf32 GEMM, D double-buffered, async A =====
// R13 ordering (measured best): wait MMA(t) -> launch cp.async A(t+1) ->
// epilogue(t) [A copy flies under it] -> cp.wait -> commit MMA(t+1).
// (MMA execution cannot overlap LDTM epilogues: TMEM port contention.)
// SMEM: hdr 1KB | B0 64KB | B1 64KB | A 64KB | sbuf 32KB = 230400.
#define G_MB0  8
#define G_MB1  16
#define G_B0   1024
#define G_B1   (G_B0 + 65536)
#define G_A    (G_B1 + 65536)
#define G_SB   (G_A + 65536)
#define G_TOTAL (G_SB + 32768)      // 230400 <= 232448

__global__ void __launch_bounds__(256, 1) gemm_mega_kernel(
    const float* __restrict__ xp, const float* __restrict__ xa,
    const float* __restrict__ Wc_f, const float* __restrict__ Ww_f,
    const float* __restrict__ Ws_f,
    float* __restrict__ out, __half* __restrict__ Hc, __half* __restrict__ Hw)
{
    extern __shared__ char smem[];
    const int tid = threadIdx.x, w = tid >> 5, lane = tid & 31;

#if USE_TC
    uint32_t sb = s2u(smem);
    char* sbuf = smem + G_SB;
    const uint32_t sA_u = sb + G_A;

    if (w == 0) {
        TC_ALLOC(sb, 512);
        TC_RELINQ();
    }
    if (tid == 0) {
        MBAR_INIT(sb + G_MB0, 1);
        MBAR_INIT(sb + G_MB1, 1);
    }

    // CTA role
    const int paper = (blockIdx.x < NCTA_P);
    const float* X;
    int t0, stride, tend, nr;
    if (paper) {
        X = xp; t0 = blockIdx.x;          stride = NCTA_P; tend = NT_P; nr = NP;
    } else {
        X = xa; t0 = blockIdx.x - NCTA_P; stride = NCTA_A; tend = NT_A; nr = NA;
    }

    // Stage B images from pre-built g_Wf (straight float4 copies)
    {
        const float* B0s = paper ? g_Wf[2] : g_Wf[1];
        for (int i = tid; i < 4096; i += 256)
            ((float4*)(smem + G_B0))[i] = ((const float4*)B0s)[i];
        if (paper)
            for (int i = tid; i < 4096; i += 256)
                ((float4*)(smem + G_B1))[i] = ((const float4*)g_Wf[0])[i];
    }
    asm volatile("fence.proxy.async.shared::cta;" ::: "memory");
    __syncthreads();

    uint32_t tmem;
    asm volatile("ld.shared.b32 %0, [%1];" : "=r"(tmem) : "r"(sb));

    const uint64_t dB0 = smem_desc(sb + G_B0);
    const uint64_t dB1 = smem_desc(sb + G_B1);
    const uint64_t dA  = smem_desc(sA_u);

    // Prologue: A(t0) + MMA into slot 0
    int t = t0;
    copy_a_async(X, t * 128, nr, sA_u, tid);
    CP_WAIT_ALL();
    asm volatile("fence.proxy.async.shared::cta;" ::: "memory");
    __syncthreads();
    if (w == 0 && elect1()) {
        issue_tf32(tmem + 0, dA, dB0);
        if (paper) issue_tf32(tmem + 128, dA, dB1);
        TC_COMMIT(sb + G_MB0);
    }

    int i = 0;
    for (; t < tend; t += stride, i++) {
        const int s  = i & 1;
        const int ph = (i >> 1) & 1;
        const int row0 = t * 128;

        MBAR_WAIT(sb + (s ? G_MB1 : G_MB0), ph);   // MMA(t) done: A free, D[s] full
        TC_FENCE_AFTER();

        // Launch async copy of A(t+1); it flies under the epilogue below.
        int tn = t + stride;
        if (tn < tend)
            copy_a_async(X, tn * 128, nr, sA_u, tid);

        // Epilogue slot s (overlaps the async A copy)
        if (paper) {
            store_d_f32(out, row0, nr, tmem + (uint32_t)s * 256,
                        sbuf, tid, w, lane);
            store_d_f16(Hc, row0, nr, tmem + (uint32_t)s * 256 + 128,
                        sbuf, tid, w, lane);
        } else {
            store_d_f16(Hw, row0, nr, tmem + (uint32_t)s * 256,
                        sbuf, tid, w, lane);
        }
        TC_FENCE_BEFORE();

        // A(t+1) landed -> issue MMA(t+1) into the other slot
        if (tn < tend) {
            CP_WAIT_ALL();
            asm volatile("fence.proxy.async.shared::cta;" ::: "memory");
            __syncthreads();
            if (w == 0 && elect1()) {
                uint32_t ds = (uint32_t)(s ^ 1) * 256;
                issue_tf32(tmem + ds, dA, dB0);
                if (paper) issue_tf32(tmem + ds + 128, dA, dB1);
                TC_COMMIT(sb + ((s ^ 1) ? G_MB1 : G_MB0));
            }
        }
    }

    __syncthreads();
    if (tid == 0) {
        MBAR_INVAL(sb + G_MB0);
        MBAR_INVAL(sb + G_MB1);
    }
    __syncthreads();
    if (w == 0) TC_DEALLOC(tmem, 512);
#else
    // -------- SIMT fallback (non-'a' PTX target only; never runs on GB300) --
    (void)smem;
    for (int t = blockIdx.x; t < NT; t += GRID_PERS) {
        const int paper = (t < NT_P);
        const int row0  = (paper ? t : t - NT_P) * 128;
        const int nr    = paper ? NP : NA;
        const float* X  = paper ? xp : xa;
        const int nw    = paper ? 2 : 1;
        for (int m = 0; m < nw; m++) {
            const float* Wf = paper ? (m ? Wc_f : Ws_f) : Ww_f;
            float acc[16][4];
            #pragma unroll
            for (int r = 0; r < 16; r++)
                acc[r][0] = acc[r][1] = acc[r][2] = acc[r][3] = 0.f;
            for (int k4 = 0; k4 < 32; k4++) {
                float4 w0 = __ldg((const float4*)(Wf + (k4 * 4 + 0) * DIM) + lane);
                float4 w1 = __ldg((const float4*)(Wf + (k4 * 4 + 1) * DIM) + lane);
                float4 w2 = __ldg((const float4*)(Wf + (k4 * 4 + 2) * DIM) + lane);
                float4 w3 = __ldg((const float4*)(Wf + (k4 * 4 + 3) * DIM) + lane);
                for (int r = 0; r < 16; r++) {
                    int gr = row0 + w + 8 * r;
                    float4 xv = (gr < nr)
                        ? __ldg((const float4*)(X + (size_t)gr * DIM) + k4)
                        : make_float4(0.f, 0.f, 0.f, 0.f);
                    acc[r][0] += xv.x * w0.x + xv.y * w1.x + xv.z * w2.x + xv.w * w3.x;
                    acc[r][1] += xv.x * w0.y + xv.y * w1.y + xv.z * w2.y + xv.w * w3.y;
                    acc[r][2] += xv.x * w0.z + xv.y * w1.z + xv.z * w2.z + xv.w * w3.z;
                    acc[r][3] += xv.x * w0.w + xv.y * w1.w + xv.z * w2.w + xv.w * w3.w;
                }
            }
            #pragma unroll
            for (int r = 0; r < 16; r++) {
                int gr = row0 + w + 8 * r;
                if (gr >= nr) continue;
                if (paper && m == 0) {
                    ((float4*)(out + (size_t)gr * DIM))[lane] =
                        make_float4(acc[r][0], acc[r][1], acc[r][2], acc[r][3]);
                } else {
                    __half* Y = paper ? Hc : Hw;
                    __half2 h01 = __floats2half2_rn(acc[r][0], acc[r][1]);
                    __half2 h23 = __floats2half2_rn(acc[r][2], acc[r][3]);
                    ((uint2*)(Y + (size_t)gr * DIM))[lane] =
                        make_uint2(*(uint32_t*)&h01, *(uint32_t*)&h23);
                }
            }
        }
    }
#endif
}

// ---------------------------------------------------------------------------
extern "C" void kernel_launch(void* const* d_in, const int* in_sizes, int n_in,
                              void* d_out, int out_size)
{
    const float* x_paper    = (const float*)d_in[0];
    const float* x_author   = (const float*)d_in[1];
    const float* W_cites    = (const float*)d_in[2];
    const float* W_writes   = (const float*)d_in[3];
    const float* W_self     = (const float*)d_in[4];
    const float* bias       = (const float*)d_in[5];
    const int*   cites_src  = (const int*)d_in[6];
    const int*   cites_dst  = (const int*)d_in[7];
    const int*   writes_src = (const int*)d_in[8];
    const int*   writes_dst = (const int*)d_in[9];
    float*       out        = (float*)d_out;

    cudaFuncSetAttribute(gemm_mega_kernel,
                         cudaFuncAttributeMaxDynamicSharedMemorySize, G_TOTAL);

    void *pHc = nullptr, *pHw = nullptr, *pCnt = nullptr;
    cudaGetSymbolAddress(&pHc, g_Hc);
    cudaGetSymbolAddress(&pHw, g_Hw);
    cudaGetSymbolAddress(&pCnt, g_cnt);

    // Fork a side stream for the CSR chain (graph-capture-legal fork/join).
    cudaStream_t s2;
    cudaStreamCreateWithFlags(&s2, cudaStreamNonBlocking);
    cudaEvent_t ev_fork, ev_join;
    cudaEventCreateWithFlags(&ev_fork, cudaEventDisableTiming);
    cudaEventCreateWithFlags(&ev_join, cudaEventDisableTiming);

    cudaEventRecord(ev_fork, 0);
    cudaStreamWaitEvent(s2, ev_fork, 0);

    // --- side stream: CSR build ---
    cudaMemsetAsync(pCnt, 0, NP * sizeof(int), s2);
    hist_kernel<<<(E2 + 255) / 256, 256, 0, s2>>>(cites_dst, writes_dst);
    scan_a_kernel<<<NBLK, 256, 0, s2>>>();
    scan_b_kernel<<<1, 512, 0, s2>>>();
    scan_c_kernel<<<NBLK, 256, 0, s2>>>();
    fill_kernel<<<(E2 + 255) / 256, 256, 0, s2>>>(cites_src, cites_dst,
                                                  writes_src, writes_dst);
    cudaEventRecord(ev_join, s2);

    // --- main stream: W images + persistent pipelined GEMM ---
    wconv_kernel<<<(3 * DIM * DIM + 255) / 256, 256>>>(W_cites, W_writes, W_self);
    gemm_mega_kernel<<<GRID_PERS, 256, G_TOTAL>>>(
        x_paper, x_author, W_cites, W_writes, W_self,
        out, (__half*)pHc, (__half*)pHw);

    // join: aggregate needs both chains
    cudaStreamWaitEvent(0, ev_join, 0);
    aggregate_kernel<<<(NP * 32 + 255) / 256, 256>>>(out, bias);

    cudaEventDestroy(ev_fork);
    cudaEventDestroy(ev_join);
    cudaStreamDestroy(s2);
}